// round 12
// baseline (speedup 1.0000x reference)
#include <cuda_runtime.h>
#include <cuda_bf16.h>

#define NB     8
#define NC     512
#define NPIX   4096      // 64*64
#define NCLS   19
#define TGT    512
#define NCHUNK 8
#define CCH    64        // channels per chunk
#define NSPLIT 16        // NCHUNK*2 global splits
#define CSPAN  32
#define NPB    592       // persistent blocks = 148*4 (<= 152*4 on GB300)

// ---------------- device scratch (static, no allocations) ----------------
__device__ unsigned char g_lab[NB*NPIX];
__device__ float g_cnt [NB*NCLS];
__device__ float g_sumS[NB*NC*NCLS];
__device__ float g_sumT[NB*NC*NCLS];
__device__ float g_nsqS[NB*NCLS];
__device__ float g_nsqT[NB*NCLS];
__device__ float g_psum[2][4096][20];          // double-buffered quarter-row sums
__device__ float g_part[NSPLIT][4][NB*NPIX];   // dotS,fsqS,dotT,fsqT partials
__device__ float g_blockred[128];
__device__ unsigned int g_bar;                 // grid barrier counter (self-reset)
__device__ unsigned int g_done;                // exit ticket (self-reset)

// ---------------- K0: nearest-resize labels + per-batch class histogram ----
__global__ void k_prep(const int* __restrict__ tgt) {
    int b = blockIdx.x;
    __shared__ int hist[NCLS];
    if (threadIdx.x < NCLS) hist[threadIdx.x] = 0;
    __syncthreads();
    for (int n = threadIdx.x; n < NPIX; n += blockDim.x) {
        int h = n >> 6, w = n & 63;
        int k = tgt[b*TGT*TGT + (h*8)*TGT + (w*8)];   // nearest: idx*8
        unsigned char lab = (k >= 0 && k < NCLS) ? (unsigned char)k : (unsigned char)255;
        g_lab[b*NPIX + n] = lab;
        if (lab != 255) atomicAdd(&hist[k], 1);
    }
    __syncthreads();
    if (threadIdx.x < NCLS) g_cnt[b*NCLS + threadIdx.x] = (float)hist[threadIdx.x];
}

// ---------------- grid barrier (all NPB blocks co-resident) ----------------
__device__ __forceinline__ void grid_bar(unsigned int target) {
    __threadfence();                 // each thread publishes its writes
    __syncthreads();
    if (threadIdx.x == 0) {
        atomicAdd(&g_bar, 1u);
        while (*((volatile unsigned int*)&g_bar) < target) __nanosleep(128);
        __threadfence();             // acquire
    }
    __syncthreads();
}

// ---------------- B sub-phase: dot/fsq for one chunk (reads L2-hot data) ---
__device__ __forceinline__ void do_B(int cc, int bid, int t,
                                     const float* __restrict__ S,
                                     const float* __restrict__ T,
                                     float* buf) {
    __syncthreads();                 // A-phase bins in buf no longer needed
    int lsp  = bid & 1;
    int b    = (bid >> 1) & 7;
    int tile = bid >> 4;             // 0..31 (128-px tiles)
    int sp   = cc*2 + lsp;
    int c0   = cc*CCH + lsp*CSPAN;
    int par  = cc & 1;
    float* shS = buf;                // 608
    float* shT = buf + 608;          // 608
    float* red = buf + 1216;         // [4 sub][8 val][64 pair] = 2048

    // stage combined class sums for this (b, 32-ch split); tile 0 also -> g_sum
    for (int idx = t; idx < 1216; idx += 256) {
        int tensor = idx >= 608;
        int e  = idx - tensor*608;
        int cl = e / 19;
        int k  = e - cl*19;
        int row = (lsp*CSPAN + cl)*16 + b*2 + tensor;
        const float (*ps)[20] = g_psum[par];
        float v = (ps[row*4+0][k] + ps[row*4+1][k])
                + (ps[row*4+2][k] + ps[row*4+3][k]);
        buf[idx] = v;
        if (tile == 0) {
            float* gs = tensor ? g_sumT : g_sumS;
            gs[(size_t)(b*NC + c0 + cl)*NCLS + k] = v;
        }
    }
    int pair = t & 63;
    int sub  = t >> 6;               // 0..3 (8 channels each)
    int px   = tile*128 + pair*2;
    unsigned char lx = g_lab[b*NPIX + px];
    unsigned char ly = g_lab[b*NPIX + px + 1];
    int k0 = (lx < NCLS) ? lx : 0;
    int k1 = (ly < NCLS) ? ly : 0;
    __syncthreads();

    const float2* pS = (const float2*)(S + (size_t)(b*NC + c0 + sub*8)*NPIX + px);
    const float2* pT = (const float2*)(T + (size_t)(b*NC + c0 + sub*8)*NPIX + px);
    const float* mS = shS + (sub*8)*NCLS;
    const float* mT = shT + (sub*8)*NCLS;

    float dS0=0,dS1=0,fS0=0,fS1=0,dT0=0,dT1=0,fT0=0,fT1=0;
    #pragma unroll
    for (int c = 0; c < 8; c++) {
        float2 vS = pS[c*(NPIX/2)];
        float2 vT = pT[c*(NPIX/2)];
        float sA = mS[c*NCLS + k0], sB = mS[c*NCLS + k1];
        float tA = mT[c*NCLS + k0], tB = mT[c*NCLS + k1];
        fS0 += vS.x*vS.x;  dS0 += vS.x*sA;
        fS1 += vS.y*vS.y;  dS1 += vS.y*sB;
        fT0 += vT.x*vT.x;  dT0 += vT.x*tA;
        fT1 += vT.y*vT.y;  dT1 += vT.y*tB;
    }
    red[(sub*8+0)*64 + pair] = dS0;
    red[(sub*8+1)*64 + pair] = dS1;
    red[(sub*8+2)*64 + pair] = fS0;
    red[(sub*8+3)*64 + pair] = fS1;
    red[(sub*8+4)*64 + pair] = dT0;
    red[(sub*8+5)*64 + pair] = dT1;
    red[(sub*8+6)*64 + pair] = fT0;
    red[(sub*8+7)*64 + pair] = fT1;
    __syncthreads();
    if (t < 64) {
        float o[8];
        #pragma unroll
        for (int v = 0; v < 8; v++)
            o[v] = (red[(0*8+v)*64+t] + red[(1*8+v)*64+t])
                 + (red[(2*8+v)*64+t] + red[(3*8+v)*64+t]);
        int gi = b*NPIX + tile*128 + t*2;
        *(float2*)&g_part[sp][0][gi] = make_float2(o[0], o[1]);
        *(float2*)&g_part[sp][1][gi] = make_float2(o[2], o[3]);
        *(float2*)&g_part[sp][2][gi] = make_float2(o[4], o[5]);
        *(float2*)&g_part[sp][3][gi] = make_float2(o[6], o[7]);
    }
}

// ---------------- K1: persistent chunked class-sums + dot/fsq -------------
__global__ __launch_bounds__(256, 4) void k_persist(const float* __restrict__ S,
                                                    const float* __restrict__ T) {
    __shared__ float buf[5120];      // A: bins[8][20][32] | B: stage 1216 + red 2048
    int t    = threadIdx.x;
    int wid  = t >> 5;
    int lane = t & 31;
    int bid  = blockIdx.x;

    for (int ch = 0; ch < NCHUNK; ch++) {
        // ---- A_ch: quarter-row class sums (DRAM stream) ----
        int wg = bid*8 + wid;
        if (wg < 4096) {
            int row = wg >> 2, quarter = wg & 3;
            int cl = row >> 4;
            int b  = (row >> 1) & 7;
            int tensor = row & 1;
            int c = ch*CCH + cl;
            const float* F = tensor ? T : S;
            float* mb = &buf[wid*640 + lane];     // [wid][k][lane], stride 32
            #pragma unroll
            for (int k = 0; k <= NCLS; k++) mb[k*32] = 0.f;
            const float4* rowp = (const float4*)(F + (size_t)(b*NC + c) * NPIX);
            const uchar4* lb   = (const uchar4*)&g_lab[b*NPIX];
            int base = quarter * 256;
            #pragma unroll
            for (int j = 0; j < 8; j++) {
                int i = base + lane + j*32;
                float4 v = rowp[i];
                uchar4 l = lb[i];
                int kx = l.x < NCLS ? l.x : NCLS;
                int ky = l.y < NCLS ? l.y : NCLS;
                int kz = l.z < NCLS ? l.z : NCLS;
                int kw = l.w < NCLS ? l.w : NCLS;
                mb[kx*32] += v.x;
                mb[ky*32] += v.y;
                mb[kz*32] += v.z;
                mb[kw*32] += v.w;
            }
            __syncwarp();
            float* psrow = g_psum[ch & 1][wg];
            #pragma unroll
            for (int k = 0; k < NCLS; k++) {
                float v = buf[wid*640 + k*32 + lane];
                #pragma unroll
                for (int o = 16; o > 0; o >>= 1) v += __shfl_down_sync(0xFFFFFFFFu, v, o);
                if (lane == 0) psrow[k] = v;
            }
        }
        // ---- B_{ch-1}: consume previous chunk while it's L2-hot ----
        if (ch > 0 && bid < 512) do_B(ch - 1, bid, t, S, T, buf);
        grid_bar((unsigned)(ch + 1) * NPB);
    }
    // final B for last chunk
    if (bid < 512) do_B(NCHUNK - 1, bid, t, S, T, buf);

    // exit ticket: last block resets counters for the next (graph) replay
    __syncthreads();
    if (t == 0) {
        __threadfence();
        unsigned int d = atomicAdd(&g_done, 1u);
        if (d == NPB - 1) { g_bar = 0; g_done = 0; }
    }
}

// ---------------- K2: per-(b,k) squared norm of class sums ----------------
__global__ void k_stats() {
    int b = blockIdx.x, k = blockIdx.y, t = threadIdx.x;
    float aS = 0.f, aT = 0.f;
    for (int c = t; c < NC; c += 256) {
        float s = g_sumS[((size_t)b*NC + c)*NCLS + k]; aS += s*s;
        float u = g_sumT[((size_t)b*NC + c)*NCLS + k]; aT += u*u;
    }
    #pragma unroll
    for (int o = 16; o > 0; o >>= 1) {
        aS += __shfl_down_sync(0xFFFFFFFFu, aS, o);
        aT += __shfl_down_sync(0xFFFFFFFFu, aT, o);
    }
    __shared__ float sS[8], sT[8];
    if ((t & 31) == 0) { sS[t >> 5] = aS; sT[t >> 5] = aT; }
    __syncthreads();
    if (t == 0) {
        float s = 0.f, u = 0.f;
        #pragma unroll
        for (int w = 0; w < 8; w++) { s += sS[w]; u += sT[w]; }
        g_nsqS[b*NCLS + k] = s;
        g_nsqT[b*NCLS + k] = u;
    }
}

// ---------------- K3: combine splits, cosine sims, per-block MSE partial ---
__global__ void k_final() {
    int t = threadIdx.x;
    int gi = blockIdx.x*256 + t;   // 128 blocks * 256 = 32768 pixels
    float dS=0,fS=0,dT=0,fT=0;
    #pragma unroll
    for (int s = 0; s < NSPLIT; s++) {
        dS += g_part[s][0][gi];
        fS += g_part[s][1][gi];
        dT += g_part[s][2][gi];
        fT += g_part[s][3][gi];
    }
    int b = gi >> 12;
    int k = g_lab[gi];
    float pS_, pT_;
    if (k < NCLS) {
        float cnt = g_cnt[b*NCLS + k];
        float inv = 1.f/(cnt + 1e-6f);
        float nfS = sqrtf(fS);
        float nmS = sqrtf(g_nsqS[b*NCLS + k]) * inv;
        pS_ = (dS*inv) / (fmaxf(nfS, 1e-8f) * fmaxf(nmS, 1e-8f));
        float nfT = sqrtf(fT);
        float nmT = sqrtf(g_nsqT[b*NCLS + k]) * inv;
        pT_ = (dT*inv) / (fmaxf(nfT, 1e-8f) * fmaxf(nmT, 1e-8f));
    } else {
        float nfS = fmaxf(sqrtf(fS), 1e-8f); pS_ = fS/(nfS*nfS);
        float nfT = fmaxf(sqrtf(fT), 1e-8f); pT_ = fT/(nfT*nfT);
    }
    float d = pS_ - pT_;
    float v = d*d;
    #pragma unroll
    for (int o = 16; o > 0; o >>= 1) v += __shfl_down_sync(0xFFFFFFFFu, v, o);
    __shared__ float sw[8];
    if ((t & 31) == 0) sw[t >> 5] = v;
    __syncthreads();
    if (t == 0) {
        float a = 0.f;
        #pragma unroll
        for (int w = 0; w < 8; w++) a += sw[w];
        g_blockred[blockIdx.x] = a;
    }
}

// ---------------- K4: final deterministic reduction to scalar -------------
__global__ void k_out(float* __restrict__ out) {
    int t = threadIdx.x;   // 128 threads
    float v = g_blockred[t];
    #pragma unroll
    for (int o = 16; o > 0; o >>= 1) v += __shfl_down_sync(0xFFFFFFFFu, v, o);
    __shared__ float s[4];
    if ((t & 31) == 0) s[t >> 5] = v;
    __syncthreads();
    if (t == 0) out[0] = (s[0] + s[1] + s[2] + s[3]) * (1.f/32768.f);
}

extern "C" void kernel_launch(void* const* d_in, const int* in_sizes, int n_in,
                              void* d_out, int out_size) {
    const float* S   = (const float*)d_in[0];
    const float* T   = (const float*)d_in[1];
    const int*   tgt = (const int*)d_in[2];
    float* out = (float*)d_out;

    k_prep   <<<NB, 256>>>(tgt);
    k_persist<<<NPB, 256>>>(S, T);
    k_stats  <<<dim3(NB, NCLS), 256>>>();
    k_final  <<<128, 256>>>();
    k_out    <<<1, 128>>>(out);
}

// round 13
// speedup vs baseline: 1.8469x; 1.8469x over previous
#include <cuda_runtime.h>
#include <cuda_bf16.h>

#define NB    8
#define NC    512
#define NPIX  4096      // 64*64
#define NCLS  19
#define TGT   512
#define NSPLIT 16
#define CSPAN (NC/NSPLIT)   // 32
#define K3_T  256
#define PXB   (K3_T*2)      // 512 pixels per K3 block
#define NTILE (NPIX/PXB)    // 8
#define NROW  (NB*NC*2)     // 8192 channel-rows (S then T)

// ---------------- device scratch (static, no allocations) ----------------
__device__ unsigned char g_lab[NB*NPIX];
__device__ float g_cnt [NB*NCLS];
__device__ float g_sumS[NB*NC*NCLS];
__device__ float g_sumT[NB*NC*NCLS];
__device__ float g_nsqS[NB*NCLS];
__device__ float g_nsqT[NB*NCLS];
__device__ float g_accum[4][NB*NPIX];   // dotS,fsqS,dotT,fsqT (L2-resident, atomics)
__device__ float g_blockred[128];

// ---- K0: labels + histogram (blocks 0..7) and accumulator zeroing (8..39) --
__global__ void k_prep(const int* __restrict__ tgt) {
    int blk = blockIdx.x;
    if (blk >= NB) {
        // zero g_accum: 32 blocks * 256 threads * 4 float4 = 512 KB
        int z = (blk - NB)*256 + threadIdx.x;      // 0..8191
        float4* p = (float4*)g_accum;               // 32768 float4 total
        #pragma unroll
        for (int j = 0; j < 4; j++) p[z*4 + j] = make_float4(0.f,0.f,0.f,0.f);
        return;
    }
    int b = blk;
    __shared__ int hist[NCLS];
    if (threadIdx.x < NCLS) hist[threadIdx.x] = 0;
    __syncthreads();
    for (int n = threadIdx.x; n < NPIX; n += blockDim.x) {
        int h = n >> 6, w = n & 63;
        int k = tgt[b*TGT*TGT + (h*8)*TGT + (w*8)];   // nearest: idx*8
        unsigned char lab = (k >= 0 && k < NCLS) ? (unsigned char)k : (unsigned char)255;
        g_lab[b*NPIX + n] = lab;
        if (lab != 255) atomicAdd(&hist[k], 1);
    }
    __syncthreads();
    if (threadIdx.x < NCLS) g_cnt[b*NCLS + threadIdx.x] = (float)hist[threadIdx.x];
}

// ---------------- K1: warp-per-channel class sums, lane-private bins ------
// bins[w][k][lane]: bank = lane -> conflict-free, no atomics, no barriers.
__global__ __launch_bounds__(256) void k_classsum(const float* __restrict__ S,
                                                  const float* __restrict__ T) {
    __shared__ float bins[8][NCLS+1][32];   // slot NCLS = trash for invalid labels
    int t    = threadIdx.x;
    int w    = t >> 5;
    int lane = t & 31;

    int r = blockIdx.x * 8 + w;          // 0..NROW-1
    int tensor = r >> 12;                // 0 = S, 1 = T
    int bc = r & (NB*NC - 1);
    int b  = bc >> 9;
    const float* F = tensor ? T : S;
    float* outp    = tensor ? g_sumT : g_sumS;

    #pragma unroll
    for (int k = 0; k <= NCLS; k++) bins[w][k][lane] = 0.f;

    const float4* row = (const float4*)(F + (size_t)bc * NPIX);
    const uchar4* lb  = (const uchar4*)&g_lab[b*NPIX];
    float* mb = &bins[w][0][lane];

    #pragma unroll 4
    for (int i = lane; i < NPIX/4; i += 32) {
        float4 v = row[i];
        uchar4 l = lb[i];
        int kx = l.x < NCLS ? l.x : NCLS;
        int ky = l.y < NCLS ? l.y : NCLS;
        int kz = l.z < NCLS ? l.z : NCLS;
        int kw = l.w < NCLS ? l.w : NCLS;
        mb[32*kx] += v.x;
        mb[32*ky] += v.y;
        mb[32*kz] += v.z;
        mb[32*kw] += v.w;
    }
    __syncwarp();

    size_t ob = (size_t)bc * NCLS;
    #pragma unroll
    for (int k = 0; k < NCLS; k++) {
        float v = bins[w][k][lane];
        #pragma unroll
        for (int o = 16; o > 0; o >>= 1) v += __shfl_down_sync(0xFFFFFFFFu, v, o);
        if (lane == 0) outp[ob + k] = v;
    }
}

// ---------------- K2: per-(b,k) squared norm of class sums ----------------
__global__ void k_stats() {
    int b = blockIdx.x, k = blockIdx.y, t = threadIdx.x;
    float aS = 0.f, aT = 0.f;
    for (int c = t; c < NC; c += 256) {
        float s = g_sumS[((size_t)b*NC + c)*NCLS + k]; aS += s*s;
        float u = g_sumT[((size_t)b*NC + c)*NCLS + k]; aT += u*u;
    }
    #pragma unroll
    for (int o = 16; o > 0; o >>= 1) {
        aS += __shfl_down_sync(0xFFFFFFFFu, aS, o);
        aT += __shfl_down_sync(0xFFFFFFFFu, aT, o);
    }
    __shared__ float sS[8], sT[8];
    if ((t & 31) == 0) { sS[t >> 5] = aS; sT[t >> 5] = aT; }
    __syncthreads();
    if (t == 0) {
        float s = 0.f, u = 0.f;
        #pragma unroll
        for (int w = 0; w < 8; w++) { s += sS[w]; u += sT[w]; }
        g_nsqS[b*NCLS + k] = s;
        g_nsqT[b*NCLS + k] = u;
    }
}

// ---------------- K3: main pass — per-pixel ||f||^2 and f·sums[class] -----
// Epilogue uses REDG float atomics into 512 KB L2-resident accumulators
// (replaces 8.4 MB of DRAM partial stores + re-read).
__global__ __launch_bounds__(K3_T) void k_main(const float* __restrict__ S,
                                               const float* __restrict__ T) {
    int tile = blockIdx.x;   // 0..NTILE-1
    int b    = blockIdx.y;   // 0..7
    int sp   = blockIdx.z;   // 0..NSPLIT-1
    __shared__ float shS[CSPAN*NCLS];   // 32*19 = 608 floats
    __shared__ float shT[CSPAN*NCLS];
    int t = threadIdx.x;
    int c0 = sp*CSPAN;

    for (int i = t; i < CSPAN*NCLS; i += K3_T) {
        shS[i] = g_sumS[((size_t)(b*NC + c0))*NCLS + i];
        shT[i] = g_sumT[((size_t)(b*NC + c0))*NCLS + i];
    }
    int px = tile*PXB + 2*t;
    unsigned char lx = g_lab[b*NPIX + px];
    unsigned char ly = g_lab[b*NPIX + px + 1];
    int k0 = (lx < NCLS) ? lx : 0;   // dot unused for invalid labels
    int k1 = (ly < NCLS) ? ly : 0;
    __syncthreads();

    const float2* pS = (const float2*)(S + ((size_t)(b*NC + c0))*NPIX + px);
    const float2* pT = (const float2*)(T + ((size_t)(b*NC + c0))*NPIX + px);

    float dS0=0,dS1=0, fS0=0,fS1=0;
    float dT0=0,dT1=0, fT0=0,fT1=0;
    #pragma unroll 8
    for (int c = 0; c < CSPAN; c++) {
        float2 vS = pS[c*(NPIX/2)];
        float2 vT = pT[c*(NPIX/2)];
        float sA = shS[c*NCLS + k0], sB = shS[c*NCLS + k1];
        float tA = shT[c*NCLS + k0], tB = shT[c*NCLS + k1];
        fS0 += vS.x*vS.x;  dS0 += vS.x*sA;
        fS1 += vS.y*vS.y;  dS1 += vS.y*sB;
        fT0 += vT.x*vT.x;  dT0 += vT.x*tA;
        fT1 += vT.y*vT.y;  dT1 += vT.y*tB;
    }
    int gi = b*NPIX + px;
    atomicAdd(&g_accum[0][gi],   dS0);
    atomicAdd(&g_accum[0][gi+1], dS1);
    atomicAdd(&g_accum[1][gi],   fS0);
    atomicAdd(&g_accum[1][gi+1], fS1);
    atomicAdd(&g_accum[2][gi],   dT0);
    atomicAdd(&g_accum[2][gi+1], dT1);
    atomicAdd(&g_accum[3][gi],   fT0);
    atomicAdd(&g_accum[3][gi+1], fT1);
}

// ---------------- K4: cosine sims + per-block MSE partial (L2 reads) ------
__global__ void k_final() {
    int t = threadIdx.x;
    int gi = blockIdx.x*256 + t;   // 128 blocks * 256 = 32768 pixels
    float dS = g_accum[0][gi];
    float fS = g_accum[1][gi];
    float dT = g_accum[2][gi];
    float fT = g_accum[3][gi];
    int b = gi >> 12;
    int k = g_lab[gi];
    float pS_, pT_;
    if (k < NCLS) {
        float cnt = g_cnt[b*NCLS + k];
        float inv = 1.f/(cnt + 1e-6f);
        float nfS = sqrtf(fS);
        float nmS = sqrtf(g_nsqS[b*NCLS + k]) * inv;
        pS_ = (dS*inv) / (fmaxf(nfS, 1e-8f) * fmaxf(nmS, 1e-8f));
        float nfT = sqrtf(fT);
        float nmT = sqrtf(g_nsqT[b*NCLS + k]) * inv;
        pT_ = (dT*inv) / (fmaxf(nfT, 1e-8f) * fmaxf(nmT, 1e-8f));
    } else {
        // invalid label: center = f  ->  cos(f, f)
        float nfS = fmaxf(sqrtf(fS), 1e-8f); pS_ = fS/(nfS*nfS);
        float nfT = fmaxf(sqrtf(fT), 1e-8f); pT_ = fT/(nfT*nfT);
    }
    float d = pS_ - pT_;
    float v = d*d;
    #pragma unroll
    for (int o = 16; o > 0; o >>= 1) v += __shfl_down_sync(0xFFFFFFFFu, v, o);
    __shared__ float sw[8];
    if ((t & 31) == 0) sw[t >> 5] = v;
    __syncthreads();
    if (t == 0) {
        float a = 0.f;
        #pragma unroll
        for (int w = 0; w < 8; w++) a += sw[w];
        g_blockred[blockIdx.x] = a;
    }
}

// ---------------- K5: final deterministic reduction to scalar -------------
__global__ void k_out(float* __restrict__ out) {
    int t = threadIdx.x;   // 128 threads
    float v = g_blockred[t];
    #pragma unroll
    for (int o = 16; o > 0; o >>= 1) v += __shfl_down_sync(0xFFFFFFFFu, v, o);
    __shared__ float s[4];
    if ((t & 31) == 0) s[t >> 5] = v;
    __syncthreads();
    if (t == 0) out[0] = (s[0] + s[1] + s[2] + s[3]) * (1.f/32768.f);
}

extern "C" void kernel_launch(void* const* d_in, const int* in_sizes, int n_in,
                              void* d_out, int out_size) {
    const float* S   = (const float*)d_in[0];
    const float* T   = (const float*)d_in[1];
    const int*   tgt = (const int*)d_in[2];
    float* out = (float*)d_out;

    k_prep    <<<NB + 32, 256>>>(tgt);
    k_classsum<<<NROW/8, 256>>>(S, T);
    k_stats   <<<dim3(NB, NCLS), 256>>>();
    k_main    <<<dim3(NTILE, NB, NSPLIT), K3_T>>>(S, T);
    k_final   <<<128, 256>>>();
    k_out     <<<1, 128>>>(out);
}